// round 1
// baseline (speedup 1.0000x reference)
#include <cuda_runtime.h>
#include <cstdint>
#include <cmath>

// ---------------------------------------------------------------------------
// Problem constants
// ---------------------------------------------------------------------------
#define BB 4
#define SS 1024
#define DD 2048
#define HH 16
#define HDIM 128
#define II 8192
#define MTOK (BB*SS)          // 4096 rows of tokens

// ---------------------------------------------------------------------------
// Scratch (static __device__ arrays: allocation-free rule)
// ---------------------------------------------------------------------------
__device__ __align__(256) float g_xln1 [MTOK*DD];
__device__ __align__(256) float g_q    [MTOK*DD];
__device__ __align__(256) float g_k    [MTOK*DD];
__device__ __align__(256) float g_v    [MTOK*DD];
__device__ __align__(256) float g_scores[(long)BB*HH*SS*SS]; // 256MB, reused as probs
__device__ __align__(256) float g_attn [MTOK*DD];
__device__ __align__(256) float g_hidden[MTOK*DD];
__device__ __align__(256) float g_yln2 [MTOK*DD];
__device__ __align__(256) float g_mid  [MTOK*II];
__device__ __align__(256) float g_wq[DD*DD], g_wk[DD*DD], g_wv[DD*DD], g_wo[DD*DD];
__device__ __align__(256) float g_w1[II*DD], g_w2[DD*II];

// ---------------------------------------------------------------------------
// Helpers
// ---------------------------------------------------------------------------
__device__ __forceinline__ float to_tf32(float x) {
    float r;
    asm("cvt.rna.tf32.f32 %0, %1;" : "=f"(r) : "f"(x));
    return r;
}

__device__ __forceinline__ void cpa16(void* sdst, const void* gsrc) {
    uint32_t s = (uint32_t)__cvta_generic_to_shared(sdst);
    asm volatile("cp.async.cg.shared.global [%0], [%1], 16;" :: "r"(s), "l"(gsrc));
}
__device__ __forceinline__ void cp_commit() { asm volatile("cp.async.commit_group;"); }
__device__ __forceinline__ void cp_wait2()  { asm volatile("cp.async.wait_group 2;"); }

__device__ __forceinline__ void mma_tf32(float c[4], const float a[4], const float b[2]) {
    const uint32_t* A = reinterpret_cast<const uint32_t*>(a);
    const uint32_t* Bp = reinterpret_cast<const uint32_t*>(b);
    asm volatile(
        "mma.sync.aligned.m16n8k8.row.col.f32.tf32.tf32.f32 "
        "{%0,%1,%2,%3}, {%4,%5,%6,%7}, {%8,%9}, {%0,%1,%2,%3};"
        : "+f"(c[0]), "+f"(c[1]), "+f"(c[2]), "+f"(c[3])
        : "r"(A[0]), "r"(A[1]), "r"(A[2]), "r"(A[3]), "r"(Bp[0]), "r"(Bp[1]));
}

// ---------------------------------------------------------------------------
// Generic TN/NN GEMM: C[M,N] = A[M,K] * op(B) (+ epilogue)
//   BKM=true : B stored [N,K], K contiguous  (x @ W.T, Q.K^T)
//   BKM=false: B stored [K,N], N contiguous  (P @ V)
// Tiles: CTA 128x128x32, 8 warps (4x2), warp tile 32x64, m16n8k8 tf32 mma.
// 3-stage cp.async pipeline. All dims are exact multiples (no predication).
// ---------------------------------------------------------------------------
enum { EPI_QKV = 0, EPI_SCORES = 1, EPI_RND = 2, EPI_BIASRES = 3, EPI_GELU = 4 };

#define SA_STRIDE 36
#define SBNN_STRIDE 136
#define SA_ELEMS (128*SA_STRIDE)     // per stage
#define SBKM_ELEMS (128*SA_STRIDE)
#define SBNN_ELEMS (32*SBNN_STRIDE)

template<bool BKM, int EPI>
__global__ void __launch_bounds__(256, 1) gemm_k(
    const float* __restrict__ A, const float* __restrict__ Bm, float* __restrict__ C,
    int lda, int ldb, int ldc, int ntk,
    long aB, long aH, long bB, long bH, long cB, long cH, long eB, long eH, int Hdiv,
    const float* __restrict__ bias, const float* __restrict__ extra, float scale)
{
    extern __shared__ float sm[];
    float* sA = sm;
    float* sB = sm + 3 * SA_ELEMS;

    const int tid = threadIdx.x;
    const int z = blockIdx.z;
    const int bz = z / Hdiv, hz = z - bz * Hdiv;

    const float* Ag = A + bz * aB + hz * aH + (long)(blockIdx.y * 128) * lda;
    const float* Bg;
    if (BKM) Bg = Bm + bz * bB + hz * bH + (long)(blockIdx.x * 128) * ldb;
    else     Bg = Bm + bz * bB + hz * bH + blockIdx.x * 128;

    const int ar = tid >> 3, ac = (tid & 7) * 4;
    const int br = BKM ? (tid >> 3) : (tid >> 5);
    const int bc = BKM ? ((tid & 7) * 4) : ((tid & 31) * 4);

    auto issue = [&](int kt, int stg) {
        const float* a0 = Ag + (long)kt * 32 + ac;
        float* sa = sA + stg * SA_ELEMS;
#pragma unroll
        for (int p = 0; p < 4; p++)
            cpa16(sa + (ar + p * 32) * SA_STRIDE + ac, a0 + (long)(ar + p * 32) * lda);
        if (BKM) {
            const float* b0 = Bg + (long)kt * 32 + bc;
            float* sb = sB + stg * SBKM_ELEMS;
#pragma unroll
            for (int p = 0; p < 4; p++)
                cpa16(sb + (br + p * 32) * SA_STRIDE + bc, b0 + (long)(br + p * 32) * ldb);
        } else {
            const float* b0 = Bg + (long)kt * 32 * ldb + bc;
            float* sb = sB + stg * SBNN_ELEMS;
#pragma unroll
            for (int p = 0; p < 4; p++)
                cpa16(sb + (br + p * 8) * SBNN_STRIDE + bc, b0 + (long)(br + p * 8) * ldb);
        }
    };

    const int warp = tid >> 5, lane = tid & 31;
    const int wm = (warp & 3) * 32;   // warp row origin within 128
    const int wn = (warp >> 2) * 64;  // warp col origin within 128
    const int g = lane >> 2, t = lane & 3;

    float acc[2][8][4];
#pragma unroll
    for (int mt = 0; mt < 2; mt++)
#pragma unroll
        for (int nt = 0; nt < 8; nt++)
#pragma unroll
            for (int i = 0; i < 4; i++) acc[mt][nt][i] = 0.f;

    issue(0, 0); cp_commit();
    issue(1, 1); cp_commit();

    for (int it = 0; it < ntk; ++it) {
        int stg = it % 3;
        if (it + 2 < ntk) issue(it + 2, (it + 2) % 3);
        cp_commit();
        cp_wait2();
        __syncthreads();

        const float* sa = sA + stg * SA_ELEMS;
        const float* sb = sB + stg * (BKM ? SBKM_ELEMS : SBNN_ELEMS);
#pragma unroll
        for (int ks = 0; ks < 4; ks++) {
            const int k0 = ks * 8;
            float af[2][4];
#pragma unroll
            for (int mt = 0; mt < 2; mt++) {
                int r0 = wm + mt * 16 + g;
                af[mt][0] = sa[r0 * SA_STRIDE + k0 + t];
                af[mt][1] = sa[(r0 + 8) * SA_STRIDE + k0 + t];
                af[mt][2] = sa[r0 * SA_STRIDE + k0 + t + 4];
                af[mt][3] = sa[(r0 + 8) * SA_STRIDE + k0 + t + 4];
            }
            float bf[8][2];
#pragma unroll
            for (int nt = 0; nt < 8; nt++) {
                int c0 = wn + nt * 8 + g;
                if (BKM) {
                    bf[nt][0] = sb[c0 * SA_STRIDE + k0 + t];
                    bf[nt][1] = sb[c0 * SA_STRIDE + k0 + t + 4];
                } else {
                    bf[nt][0] = sb[(k0 + t) * SBNN_STRIDE + c0];
                    bf[nt][1] = sb[(k0 + t + 4) * SBNN_STRIDE + c0];
                }
            }
#pragma unroll
            for (int mt = 0; mt < 2; mt++)
#pragma unroll
                for (int nt = 0; nt < 8; nt++)
                    mma_tf32(acc[mt][nt], af[mt], bf[nt]);
        }
        __syncthreads();
    }

    // Epilogue
    const long co = bz * cB + hz * cH;
    const long eo = bz * eB + hz * eH;
    const int mbase = blockIdx.y * 128 + wm;
    const int nbase = blockIdx.x * 128 + wn;

#pragma unroll
    for (int mt = 0; mt < 2; mt++) {
#pragma unroll
        for (int half = 0; half < 2; half++) {
            const int row = mbase + mt * 16 + g + half * 8;
#pragma unroll
            for (int nt = 0; nt < 8; nt++) {
                const int col = nbase + nt * 8 + 2 * t;
                float v0 = acc[mt][nt][half * 2 + 0];
                float v1 = acc[mt][nt][half * 2 + 1];
                if (EPI == EPI_QKV) {
                    v0 = to_tf32((v0 + bias[col]) * scale);
                    v1 = to_tf32((v1 + bias[col + 1]) * scale);
                } else if (EPI == EPI_SCORES) {
                    if (extra[eo + col]     == 0.f) v0 += -3.4028234663852886e38f;
                    if (extra[eo + col + 1] == 0.f) v1 += -3.4028234663852886e38f;
                } else if (EPI == EPI_RND) {
                    v0 = to_tf32(v0);
                    v1 = to_tf32(v1);
                } else if (EPI == EPI_BIASRES) {
                    v0 += bias[col]     + extra[eo + (long)row * ldc + col];
                    v1 += bias[col + 1] + extra[eo + (long)row * ldc + col + 1];
                } else if (EPI == EPI_GELU) {
                    v0 += bias[col];
                    v1 += bias[col + 1];
                    v0 = to_tf32(0.5f * v0 * (1.f + erff(v0 * 0.7071067811865476f)));
                    v1 = to_tf32(0.5f * v1 * (1.f + erff(v1 * 0.7071067811865476f)));
                }
                float2 vv = make_float2(v0, v1);
                *(float2*)(C + co + (long)row * ldc + col) = vv;
            }
        }
    }
}

// ---------------------------------------------------------------------------
// LayerNorm: one CTA (256 thr) per row of 2048; output rna-rounded to tf32.
// ---------------------------------------------------------------------------
__global__ void ln_kernel(const float* __restrict__ x, const float* __restrict__ w,
                          const float* __restrict__ b, float* __restrict__ out)
{
    __shared__ float s1[8], s2[8];
    const int row = blockIdx.x, tid = threadIdx.x;
    const int lane = tid & 31, wid = tid >> 5;
    const float4* xr = (const float4*)(x + (long)row * DD);
    float4 v0 = xr[tid], v1 = xr[tid + 256];

    float s = v0.x + v0.y + v0.z + v0.w + v1.x + v1.y + v1.z + v1.w;
    float q = v0.x*v0.x + v0.y*v0.y + v0.z*v0.z + v0.w*v0.w
            + v1.x*v1.x + v1.y*v1.y + v1.z*v1.z + v1.w*v1.w;
#pragma unroll
    for (int o = 16; o; o >>= 1) {
        s += __shfl_xor_sync(0xffffffffu, s, o);
        q += __shfl_xor_sync(0xffffffffu, q, o);
    }
    if (lane == 0) { s1[wid] = s; s2[wid] = q; }
    __syncthreads();
    if (tid < 8) {
        s = s1[tid]; q = s2[tid];
#pragma unroll
        for (int o = 4; o; o >>= 1) {
            s += __shfl_xor_sync(0xffu, s, o);
            q += __shfl_xor_sync(0xffu, q, o);
        }
        if (tid == 0) { s1[0] = s; s2[0] = q; }
    }
    __syncthreads();
    const float mu = s1[0] * (1.f / DD);
    const float var = s2[0] * (1.f / DD) - mu * mu;
    const float r = rsqrtf(var + 1e-5f);

    float4 o0, o1;
    int c0 = tid * 4, c1 = (tid + 256) * 4;
    o0.x = to_tf32((v0.x - mu) * r * w[c0+0] + b[c0+0]);
    o0.y = to_tf32((v0.y - mu) * r * w[c0+1] + b[c0+1]);
    o0.z = to_tf32((v0.z - mu) * r * w[c0+2] + b[c0+2]);
    o0.w = to_tf32((v0.w - mu) * r * w[c0+3] + b[c0+3]);
    o1.x = to_tf32((v1.x - mu) * r * w[c1+0] + b[c1+0]);
    o1.y = to_tf32((v1.y - mu) * r * w[c1+1] + b[c1+1]);
    o1.z = to_tf32((v1.z - mu) * r * w[c1+2] + b[c1+2]);
    o1.w = to_tf32((v1.w - mu) * r * w[c1+3] + b[c1+3]);
    float4* orow = (float4*)(out + (long)row * DD);
    orow[tid] = o0; orow[tid + 256] = o1;
}

// ---------------------------------------------------------------------------
// Softmax over rows of 1024 (in-place on scores; output rna tf32-rounded probs)
// ---------------------------------------------------------------------------
__global__ void softmax_kernel(float* __restrict__ sc)
{
    __shared__ float red[8];
    const long row = blockIdx.x;
    float4* p = (float4*)(sc + row * (long)SS);
    const int tid = threadIdx.x, lane = tid & 31, wid = tid >> 5;
    float4 v = p[tid];

    float m = fmaxf(fmaxf(v.x, v.y), fmaxf(v.z, v.w));
#pragma unroll
    for (int o = 16; o; o >>= 1) m = fmaxf(m, __shfl_xor_sync(0xffffffffu, m, o));
    if (lane == 0) red[wid] = m;
    __syncthreads();
    if (tid < 8) {
        m = red[tid];
#pragma unroll
        for (int o = 4; o; o >>= 1) m = fmaxf(m, __shfl_xor_sync(0xffu, m, o));
        if (tid == 0) red[0] = m;
    }
    __syncthreads();
    const float M = red[0];
    __syncthreads();

    v.x = expf(v.x - M); v.y = expf(v.y - M);
    v.z = expf(v.z - M); v.w = expf(v.w - M);
    float s = v.x + v.y + v.z + v.w;
#pragma unroll
    for (int o = 16; o; o >>= 1) s += __shfl_xor_sync(0xffffffffu, s, o);
    if (lane == 0) red[wid] = s;
    __syncthreads();
    if (tid < 8) {
        s = red[tid];
#pragma unroll
        for (int o = 4; o; o >>= 1) s += __shfl_xor_sync(0xffu, s, o);
        if (tid == 0) red[0] = s;
    }
    __syncthreads();
    const float inv = 1.f / red[0];
    v.x = to_tf32(v.x * inv); v.y = to_tf32(v.y * inv);
    v.z = to_tf32(v.z * inv); v.w = to_tf32(v.w * inv);
    p[tid] = v;
}

// ---------------------------------------------------------------------------
// Weight pre-rounding (fp32 -> rna tf32 values in fp32 container)
// ---------------------------------------------------------------------------
__global__ void round_tf32_kernel(const float* __restrict__ in, float* __restrict__ out, int n4)
{
    int i = blockIdx.x * blockDim.x + threadIdx.x;
    if (i < n4) {
        float4 v = ((const float4*)in)[i];
        v.x = to_tf32(v.x); v.y = to_tf32(v.y);
        v.z = to_tf32(v.z); v.w = to_tf32(v.w);
        ((float4*)out)[i] = v;
    }
}

// ---------------------------------------------------------------------------
// Host launch
// ---------------------------------------------------------------------------
static const int SMEM_KM = 3 * (SA_ELEMS + SBKM_ELEMS) * 4;   // 110592
static const int SMEM_NN = 3 * (SA_ELEMS + SBNN_ELEMS) * 4;   // 107520

extern "C" void kernel_launch(void* const* d_in, const int* in_sizes, int n_in,
                              void* d_out, int out_size)
{
    const float* hid   = (const float*)d_in[1];   // hidden_states
    const float* amask = (const float*)d_in[2];   // attention_mask
    const float* Wq = (const float*)d_in[4];  const float* bq = (const float*)d_in[5];
    const float* Wk = (const float*)d_in[6];  const float* bk = (const float*)d_in[7];
    const float* Wv = (const float*)d_in[8];  const float* bv = (const float*)d_in[9];
    const float* Wo = (const float*)d_in[10]; const float* bo = (const float*)d_in[11];
    const float* l1w = (const float*)d_in[12]; const float* l1b = (const float*)d_in[13];
    const float* l2w = (const float*)d_in[14]; const float* l2b = (const float*)d_in[15];
    const float* W1 = (const float*)d_in[16]; const float* b1 = (const float*)d_in[17];
    const float* W2 = (const float*)d_in[18]; const float* b2 = (const float*)d_in[19];
    float* out = (float*)d_out;

    void* p;
    cudaGetSymbolAddress(&p, g_xln1);  float* xln1 = (float*)p;
    cudaGetSymbolAddress(&p, g_q);     float* q    = (float*)p;
    cudaGetSymbolAddress(&p, g_k);     float* k    = (float*)p;
    cudaGetSymbolAddress(&p, g_v);     float* v    = (float*)p;
    cudaGetSymbolAddress(&p, g_scores);float* sc   = (float*)p;
    cudaGetSymbolAddress(&p, g_attn);  float* attn = (float*)p;
    cudaGetSymbolAddress(&p, g_hidden);float* hd2  = (float*)p;
    cudaGetSymbolAddress(&p, g_yln2);  float* yln2 = (float*)p;
    cudaGetSymbolAddress(&p, g_mid);   float* mid  = (float*)p;
    cudaGetSymbolAddress(&p, g_wq);    float* wq   = (float*)p;
    cudaGetSymbolAddress(&p, g_wk);    float* wk   = (float*)p;
    cudaGetSymbolAddress(&p, g_wv);    float* wv   = (float*)p;
    cudaGetSymbolAddress(&p, g_wo);    float* wo   = (float*)p;
    cudaGetSymbolAddress(&p, g_w1);    float* w1   = (float*)p;
    cudaGetSymbolAddress(&p, g_w2);    float* w2   = (float*)p;

    cudaFuncSetAttribute((const void*)gemm_k<true,  EPI_QKV>,     cudaFuncAttributeMaxDynamicSharedMemorySize, SMEM_KM);
    cudaFuncSetAttribute((const void*)gemm_k<true,  EPI_SCORES>,  cudaFuncAttributeMaxDynamicSharedMemorySize, SMEM_KM);
    cudaFuncSetAttribute((const void*)gemm_k<false, EPI_RND>,     cudaFuncAttributeMaxDynamicSharedMemorySize, SMEM_NN);
    cudaFuncSetAttribute((const void*)gemm_k<true,  EPI_BIASRES>, cudaFuncAttributeMaxDynamicSharedMemorySize, SMEM_KM);
    cudaFuncSetAttribute((const void*)gemm_k<true,  EPI_GELU>,    cudaFuncAttributeMaxDynamicSharedMemorySize, SMEM_KM);

    const dim3 blk(256);

    // 0) round weights to tf32 (rna) — removes truncation bias in the mma
    round_tf32_kernel<<<(DD*DD/4 + 255)/256, 256>>>(Wq, wq, DD*DD/4);
    round_tf32_kernel<<<(DD*DD/4 + 255)/256, 256>>>(Wk, wk, DD*DD/4);
    round_tf32_kernel<<<(DD*DD/4 + 255)/256, 256>>>(Wv, wv, DD*DD/4);
    round_tf32_kernel<<<(DD*DD/4 + 255)/256, 256>>>(Wo, wo, DD*DD/4);
    round_tf32_kernel<<<(II*DD/4 + 255)/256, 256>>>(W1, w1, II*DD/4);
    round_tf32_kernel<<<(II*DD/4 + 255)/256, 256>>>(W2, w2, II*DD/4);

    // 1) LN1
    ln_kernel<<<MTOK, 256>>>(hid, l1w, l1b, xln1);

    const float qscale = 0.08838834764831845f;  // 128^-0.5

    // 2-4) Q, K, V projections  [4096x2048] = xln1 @ W.T
    gemm_k<true, EPI_QKV><<<dim3(16, 32, 1), blk, SMEM_KM>>>(
        xln1, wq, q, DD, DD, DD, 64, 0,0,0,0,0,0,0,0, 1, bq, nullptr, qscale);
    gemm_k<true, EPI_QKV><<<dim3(16, 32, 1), blk, SMEM_KM>>>(
        xln1, wk, k, DD, DD, DD, 64, 0,0,0,0,0,0,0,0, 1, bk, nullptr, 1.0f);
    gemm_k<true, EPI_QKV><<<dim3(16, 32, 1), blk, SMEM_KM>>>(
        xln1, wv, v, DD, DD, DD, 64, 0,0,0,0,0,0,0,0, 1, bv, nullptr, 1.0f);

    // 5) scores[bh][1024,1024] = q_bh @ k_bh^T (+mask)
    gemm_k<true, EPI_SCORES><<<dim3(8, 8, BB*HH), blk, SMEM_KM>>>(
        q, k, sc, DD, DD, SS, 4,
        (long)SS*DD, HDIM, (long)SS*DD, HDIM,
        (long)HH*SS*SS, (long)SS*SS, (long)SS, 0, HH,
        nullptr, amask, 1.0f);

    // 6) softmax rows (in-place -> probs)
    softmax_kernel<<<BB*HH*SS, 256>>>(sc);

    // 7) attn[bh][1024,128] = P @ V  (NN)
    gemm_k<false, EPI_RND><<<dim3(1, 8, BB*HH), blk, SMEM_NN>>>(
        sc, v, attn, SS, DD, DD, 32,
        (long)HH*SS*SS, (long)SS*SS, (long)SS*DD, HDIM,
        (long)SS*DD, HDIM, 0, 0, HH,
        nullptr, nullptr, 1.0f);

    // 8) hidden = residual + attn @ Wo.T + bo
    gemm_k<true, EPI_BIASRES><<<dim3(16, 32, 1), blk, SMEM_KM>>>(
        attn, wo, hd2, DD, DD, DD, 64, 0,0,0,0,0,0,0,0, 1, bo, hid, 1.0f);

    // 9) LN2
    ln_kernel<<<MTOK, 256>>>(hd2, l2w, l2b, yln2);

    // 10) mid = gelu(yln2 @ W1.T + b1)  [4096x8192]
    gemm_k<true, EPI_GELU><<<dim3(64, 32, 1), blk, SMEM_KM>>>(
        yln2, w1, mid, DD, DD, II, 64, 0,0,0,0,0,0,0,0, 1, b1, nullptr, 1.0f);

    // 11) out = hidden + mid @ W2.T + b2  [4096x2048], K=8192
    gemm_k<true, EPI_BIASRES><<<dim3(16, 32, 1), blk, SMEM_KM>>>(
        mid, w2, out, II, II, DD, 256, 0,0,0,0,0,0,0,0, 1, b2, hd2, 1.0f);
}

// round 4
// speedup vs baseline: 1.1421x; 1.1421x over previous
#include <cuda_runtime.h>
#include <cstdint>
#include <cmath>

// ---------------------------------------------------------------------------
// Problem constants
// ---------------------------------------------------------------------------
#define BB 4
#define SS 1024
#define DD 2048
#define HH 16
#define HDIM 128
#define II 8192
#define MTOK (BB*SS)

// ---------------------------------------------------------------------------
// Scratch
// ---------------------------------------------------------------------------
__device__ __align__(256) float g_xln1 [MTOK*DD];
__device__ __align__(256) float g_q    [MTOK*DD];
__device__ __align__(256) float g_k    [MTOK*DD];
__device__ __align__(256) float g_v    [MTOK*DD];
__device__ __align__(256) float g_scores[(long)BB*HH*SS*SS];
__device__ __align__(256) float g_attn [MTOK*DD];
__device__ __align__(256) float g_hidden[MTOK*DD];
__device__ __align__(256) float g_yln2 [MTOK*DD];
__device__ __align__(256) float g_mid  [MTOK*II];
__device__ __align__(256) float g_wqkv[3*DD*DD];         // Wq|Wk|Wv concatenated (rounded)
__device__ __align__(256) float g_wo[DD*DD];
__device__ __align__(256) float g_w1[II*DD], g_w2[DD*II];

// ---------------------------------------------------------------------------
// Helpers
// ---------------------------------------------------------------------------
__device__ __forceinline__ float to_tf32(float x) {
    float r;
    asm("cvt.rna.tf32.f32 %0, %1;" : "=f"(r) : "f"(x));
    return r;
}
__device__ __forceinline__ void cpa16(void* sdst, const void* gsrc) {
    uint32_t s = (uint32_t)__cvta_generic_to_shared(sdst);
    asm volatile("cp.async.cg.shared.global [%0], [%1], 16;" :: "r"(s), "l"(gsrc));
}
__device__ __forceinline__ void cp_commit() { asm volatile("cp.async.commit_group;"); }
__device__ __forceinline__ void cp_wait2()  { asm volatile("cp.async.wait_group 2;"); }

__device__ __forceinline__ void mma_tf32(float c[4], const float a[4], const float b[2]) {
    const uint32_t* A = reinterpret_cast<const uint32_t*>(a);
    const uint32_t* Bp = reinterpret_cast<const uint32_t*>(b);
    asm volatile(
        "mma.sync.aligned.m16n8k8.row.col.f32.tf32.tf32.f32 "
        "{%0,%1,%2,%3}, {%4,%5,%6,%7}, {%8,%9}, {%0,%1,%2,%3};"
        : "+f"(c[0]), "+f"(c[1]), "+f"(c[2]), "+f"(c[3])
        : "r"(A[0]), "r"(A[1]), "r"(A[2]), "r"(A[3]), "r"(Bp[0]), "r"(Bp[1]));
}

enum { EPI_QKV3 = 0, EPI_SCORES = 1, EPI_RND = 2, EPI_BIASRES = 3, EPI_GELU = 4 };

// ===========================================================================
// Big TN GEMM: C[M, N] = A[M,K] @ B[N,K]^T, fused epilogue.
// CTA 128x256x32, 8 warps (2M x 4N), warp tile 64x64, acc[4][8][4].
// 3-stage cp.async pipeline. All dims exact multiples.
// Row stride 36 floats in smem (144B = 16B aligned, conflict-free frags).
// ===========================================================================
#define GB_AS 36
#define GB_A_ELEMS (128*GB_AS)            // per stage
#define GB_B_ELEMS (256*GB_AS)
#define GB_SMEM (3*(GB_A_ELEMS+GB_B_ELEMS)*4)   // 165888 bytes

template<int EPI>
__global__ void __launch_bounds__(256, 1) gemm_big(
    const float* __restrict__ A, const float* __restrict__ Bw,
    float* __restrict__ C0, float* __restrict__ C1, float* __restrict__ C2,
    int K, int ldc,
    const float* __restrict__ bias0, const float* __restrict__ bias1,
    const float* __restrict__ bias2, const float* __restrict__ extra, float scale)
{
    extern __shared__ float sm[];
    float* sA = sm;
    float* sB = sm + 3 * GB_A_ELEMS;

    const int tid = threadIdx.x;
    const int ntk = K >> 5;

    const float* Ab = A + (long)blockIdx.y * 128 * K;
    const float* Bb = Bw + (long)blockIdx.x * 256 * K;

    // load mapping: 16B chunks; chunk c -> row c>>3, 4-float col (c&7)*4
    auto issue = [&](int kt, int stg) {
        float* sa = sA + stg * GB_A_ELEMS;
        const float* ag = Ab + (long)kt * 32;
#pragma unroll
        for (int i = 0; i < 4; i++) {
            int c = tid + i * 256;                 // 0..1023
            int r = c >> 3, cc = (c & 7) * 4;
            cpa16(sa + r * GB_AS + cc, ag + (long)r * K + cc);
        }
        float* sb = sB + stg * GB_B_ELEMS;
        const float* bg = Bb + (long)kt * 32;
#pragma unroll
        for (int i = 0; i < 8; i++) {
            int c = tid + i * 256;                 // 0..2047
            int r = c >> 3, cc = (c & 7) * 4;
            cpa16(sb + r * GB_AS + cc, bg + (long)r * K + cc);
        }
    };

    const int warp = tid >> 5, lane = tid & 31;
    const int wm = (warp & 1) * 64;       // 2 warps along M
    const int wn = (warp >> 1) * 64;      // 4 warps along N
    const int g = lane >> 2, t = lane & 3;

    float acc[4][8][4];
#pragma unroll
    for (int mt = 0; mt < 4; mt++)
#pragma unroll
        for (int nt = 0; nt < 8; nt++)
#pragma unroll
            for (int i = 0; i < 4; i++) acc[mt][nt][i] = 0.f;

    issue(0, 0); cp_commit();
    issue(1, 1); cp_commit();

    for (int it = 0; it < ntk; ++it) {
        const int stg = it % 3;
        if (it + 2 < ntk) issue(it + 2, (it + 2) % 3);
        cp_commit();
        cp_wait2();
        __syncthreads();

        const float* sa = sA + stg * GB_A_ELEMS;
        const float* sb = sB + stg * GB_B_ELEMS;
#pragma unroll
        for (int ks = 0; ks < 4; ks++) {
            const int k0 = ks * 8;
            float af[4][4];
#pragma unroll
            for (int mt = 0; mt < 4; mt++) {
                const int r0 = wm + mt * 16 + g;
                af[mt][0] = sa[r0 * GB_AS + k0 + t];
                af[mt][1] = sa[(r0 + 8) * GB_AS + k0 + t];
                af[mt][2] = sa[r0 * GB_AS + k0 + t + 4];
                af[mt][3] = sa[(r0 + 8) * GB_AS + k0 + t + 4];
            }
            float bf[8][2];
#pragma unroll
            for (int nt = 0; nt < 8; nt++) {
                const int c0 = wn + nt * 8 + g;
                bf[nt][0] = sb[c0 * GB_AS + k0 + t];
                bf[nt][1] = sb[c0 * GB_AS + k0 + t + 4];
            }
#pragma unroll
            for (int mt = 0; mt < 4; mt++)
#pragma unroll
                for (int nt = 0; nt < 8; nt++)
                    mma_tf32(acc[mt][nt], af[mt], bf[nt]);
        }
        __syncthreads();
    }

    // ---------------- epilogue ----------------
    const int nbase = blockIdx.x * 256;           // global col of CTA
    const int mbase = blockIdx.y * 128 + wm;

    float* dst = C0;
    const float* bs = bias0;
    float sc = scale;
    int nloc = nbase;
    if (EPI == EPI_QKV3) {
        const int seg = nbase >> 11;              // CTA fully inside one of q/k/v
        nloc = nbase & 2047;
        if (seg == 1) { dst = C1; bs = bias1; sc = 1.0f; }
        else if (seg == 2) { dst = C2; bs = bias2; sc = 1.0f; }
    }

#pragma unroll
    for (int mt = 0; mt < 4; mt++) {
#pragma unroll
        for (int half = 0; half < 2; half++) {
            const int row = mbase + mt * 16 + g + half * 8;
            const long crow = (long)row * ldc;
#pragma unroll
            for (int nt = 0; nt < 8; nt++) {
                const int cc = wn + nt * 8 + 2 * t;        // col within CTA
                const int col = nloc + cc;
                float v0 = acc[mt][nt][half * 2 + 0];
                float v1 = acc[mt][nt][half * 2 + 1];
                if (EPI == EPI_QKV3) {
                    v0 = to_tf32((v0 + bs[col]) * sc);
                    v1 = to_tf32((v1 + bs[col + 1]) * sc);
                } else if (EPI == EPI_BIASRES) {
                    v0 += bs[col]     + extra[crow + col];
                    v1 += bs[col + 1] + extra[crow + col + 1];
                } else if (EPI == EPI_GELU) {
                    v0 += bs[col];
                    v1 += bs[col + 1];
                    v0 = to_tf32(0.5f * v0 * (1.f + erff(v0 * 0.7071067811865476f)));
                    v1 = to_tf32(0.5f * v1 * (1.f + erff(v1 * 0.7071067811865476f)));
                }
                *(float2*)(dst + crow + col) = make_float2(v0, v1);
            }
        }
    }
}

// ===========================================================================
// SIMT GEMM for attention (scores QK^T and P@V) — unchanged from passing R1
// ===========================================================================
#define SA_STRIDE 36
#define SBNN_STRIDE 136
#define SA_ELEMS (128*SA_STRIDE)
#define SBKM_ELEMS (128*SA_STRIDE)
#define SBNN_ELEMS (32*SBNN_STRIDE)

template<bool BKM, int EPI>
__global__ void __launch_bounds__(256, 1) gemm_k(
    const float* __restrict__ A, const float* __restrict__ Bm, float* __restrict__ C,
    int lda, int ldb, int ldc, int ntk,
    long aB, long aH, long bB, long bH, long cB, long cH, long eB, long eH, int Hdiv,
    const float* __restrict__ bias, const float* __restrict__ extra, float scale)
{
    extern __shared__ float sm[];
    float* sA = sm;
    float* sB = sm + 3 * SA_ELEMS;

    const int tid = threadIdx.x;
    const int z = blockIdx.z;
    const int bz = z / Hdiv, hz = z - bz * Hdiv;

    const float* Ag = A + bz * aB + hz * aH + (long)(blockIdx.y * 128) * lda;
    const float* Bg;
    if (BKM) Bg = Bm + bz * bB + hz * bH + (long)(blockIdx.x * 128) * ldb;
    else     Bg = Bm + bz * bB + hz * bH + blockIdx.x * 128;

    const int ar = tid >> 3, ac = (tid & 7) * 4;
    const int br = BKM ? (tid >> 3) : (tid >> 5);
    const int bc = BKM ? ((tid & 7) * 4) : ((tid & 31) * 4);

    auto issue = [&](int kt, int stg) {
        const float* a0 = Ag + (long)kt * 32 + ac;
        float* sa = sA + stg * SA_ELEMS;
#pragma unroll
        for (int p = 0; p < 4; p++)
            cpa16(sa + (ar + p * 32) * SA_STRIDE + ac, a0 + (long)(ar + p * 32) * lda);
        if (BKM) {
            const float* b0 = Bg + (long)kt * 32 + bc;
            float* sb = sB + stg * SBKM_ELEMS;
#pragma unroll
            for (int p = 0; p < 4; p++)
                cpa16(sb + (br + p * 32) * SA_STRIDE + bc, b0 + (long)(br + p * 32) * ldb);
        } else {
            const float* b0 = Bg + (long)kt * 32 * ldb + bc;
            float* sb = sB + stg * SBNN_ELEMS;
#pragma unroll
            for (int p = 0; p < 4; p++)
                cpa16(sb + (br + p * 8) * SBNN_STRIDE + bc, b0 + (long)(br + p * 8) * ldb);
        }
    };

    const int warp = tid >> 5, lane = tid & 31;
    const int wm = (warp & 3) * 32;
    const int wn = (warp >> 2) * 64;
    const int g = lane >> 2, t = lane & 3;

    float acc[2][8][4];
#pragma unroll
    for (int mt = 0; mt < 2; mt++)
#pragma unroll
        for (int nt = 0; nt < 8; nt++)
#pragma unroll
            for (int i = 0; i < 4; i++) acc[mt][nt][i] = 0.f;

    issue(0, 0); cp_commit();
    issue(1, 1); cp_commit();

    for (int it = 0; it < ntk; ++it) {
        int stg = it % 3;
        if (it + 2 < ntk) issue(it + 2, (it + 2) % 3);
        cp_commit();
        cp_wait2();
        __syncthreads();

        const float* sa = sA + stg * SA_ELEMS;
        const float* sb = sB + stg * (BKM ? SBKM_ELEMS : SBNN_ELEMS);
#pragma unroll
        for (int ks = 0; ks < 4; ks++) {
            const int k0 = ks * 8;
            float af[2][4];
#pragma unroll
            for (int mt = 0; mt < 2; mt++) {
                int r0 = wm + mt * 16 + g;
                af[mt][0] = sa[r0 * SA_STRIDE + k0 + t];
                af[mt][1] = sa[(r0 + 8) * SA_STRIDE + k0 + t];
                af[mt][2] = sa[r0 * SA_STRIDE + k0 + t + 4];
                af[mt][3] = sa[(r0 + 8) * SA_STRIDE + k0 + t + 4];
            }
            float bf[8][2];
#pragma unroll
            for (int nt = 0; nt < 8; nt++) {
                int c0 = wn + nt * 8 + g;
                if (BKM) {
                    bf[nt][0] = sb[c0 * SA_STRIDE + k0 + t];
                    bf[nt][1] = sb[c0 * SA_STRIDE + k0 + t + 4];
                } else {
                    bf[nt][0] = sb[(k0 + t) * SBNN_STRIDE + c0];
                    bf[nt][1] = sb[(k0 + t + 4) * SBNN_STRIDE + c0];
                }
            }
#pragma unroll
            for (int mt = 0; mt < 2; mt++)
#pragma unroll
                for (int nt = 0; nt < 8; nt++)
                    mma_tf32(acc[mt][nt], af[mt], bf[nt]);
        }
        __syncthreads();
    }

    const long co = bz * cB + hz * cH;
    const long eo = bz * eB + hz * eH;
    const int mbase = blockIdx.y * 128 + wm;
    const int nbase = blockIdx.x * 128 + wn;

#pragma unroll
    for (int mt = 0; mt < 2; mt++) {
#pragma unroll
        for (int half = 0; half < 2; half++) {
            const int row = mbase + mt * 16 + g + half * 8;
#pragma unroll
            for (int nt = 0; nt < 8; nt++) {
                const int col = nbase + nt * 8 + 2 * t;
                float v0 = acc[mt][nt][half * 2 + 0];
                float v1 = acc[mt][nt][half * 2 + 1];
                if (EPI == EPI_SCORES) {
                    if (extra[eo + col]     == 0.f) v0 += -3.4028234663852886e38f;
                    if (extra[eo + col + 1] == 0.f) v1 += -3.4028234663852886e38f;
                } else if (EPI == EPI_RND) {
                    v0 = to_tf32(v0);
                    v1 = to_tf32(v1);
                }
                *(float2*)(C + co + (long)row * ldc + col) = make_float2(v0, v1);
            }
        }
    }
}

// ---------------------------------------------------------------------------
// LayerNorm (tf32-rna rounded output)
// ---------------------------------------------------------------------------
__global__ void ln_kernel(const float* __restrict__ x, const float* __restrict__ w,
                          const float* __restrict__ b, float* __restrict__ out)
{
    __shared__ float s1[8], s2[8];
    const int row = blockIdx.x, tid = threadIdx.x;
    const int lane = tid & 31, wid = tid >> 5;
    const float4* xr = (const float4*)(x + (long)row * DD);
    float4 v0 = xr[tid], v1 = xr[tid + 256];

    float s = v0.x + v0.y + v0.z + v0.w + v1.x + v1.y + v1.z + v1.w;
    float q = v0.x*v0.x + v0.y*v0.y + v0.z*v0.z + v0.w*v0.w
            + v1.x*v1.x + v1.y*v1.y + v1.z*v1.z + v1.w*v1.w;
#pragma unroll
    for (int o = 16; o; o >>= 1) {
        s += __shfl_xor_sync(0xffffffffu, s, o);
        q += __shfl_xor_sync(0xffffffffu, q, o);
    }
    if (lane == 0) { s1[wid] = s; s2[wid] = q; }
    __syncthreads();
    if (tid < 8) {
        s = s1[tid]; q = s2[tid];
#pragma unroll
        for (int o = 4; o; o >>= 1) {
            s += __shfl_xor_sync(0xffu, s, o);
            q += __shfl_xor_sync(0xffu, q, o);
        }
        if (tid == 0) { s1[0] = s; s2[0] = q; }
    }
    __syncthreads();
    const float mu = s1[0] * (1.f / DD);
    const float var = s2[0] * (1.f / DD) - mu * mu;
    const float r = rsqrtf(var + 1e-5f);

    float4 o0, o1;
    int c0 = tid * 4, c1 = (tid + 256) * 4;
    o0.x = to_tf32((v0.x - mu) * r * w[c0+0] + b[c0+0]);
    o0.y = to_tf32((v0.y - mu) * r * w[c0+1] + b[c0+1]);
    o0.z = to_tf32((v0.z - mu) * r * w[c0+2] + b[c0+2]);
    o0.w = to_tf32((v0.w - mu) * r * w[c0+3] + b[c0+3]);
    o1.x = to_tf32((v1.x - mu) * r * w[c1+0] + b[c1+0]);
    o1.y = to_tf32((v1.y - mu) * r * w[c1+1] + b[c1+1]);
    o1.z = to_tf32((v1.z - mu) * r * w[c1+2] + b[c1+2]);
    o1.w = to_tf32((v1.w - mu) * r * w[c1+3] + b[c1+3]);
    float4* orow = (float4*)(out + (long)row * DD);
    orow[tid] = o0; orow[tid + 256] = o1;
}

// ---------------------------------------------------------------------------
// Softmax (tf32-rna rounded probs)
// ---------------------------------------------------------------------------
__global__ void softmax_kernel(float* __restrict__ sc)
{
    __shared__ float red[8];
    const long row = blockIdx.x;
    float4* p = (float4*)(sc + row * (long)SS);
    const int tid = threadIdx.x, lane = tid & 31, wid = tid >> 5;
    float4 v = p[tid];

    float m = fmaxf(fmaxf(v.x, v.y), fmaxf(v.z, v.w));
#pragma unroll
    for (int o = 16; o; o >>= 1) m = fmaxf(m, __shfl_xor_sync(0xffffffffu, m, o));
    if (lane == 0) red[wid] = m;
    __syncthreads();
    if (tid < 8) {
        m = red[tid];
#pragma unroll
        for (int o = 4; o; o >>= 1) m = fmaxf(m, __shfl_xor_sync(0xffu, m, o));
        if (tid == 0) red[0] = m;
    }
    __syncthreads();
    const float M = red[0];
    __syncthreads();

    v.x = expf(v.x - M); v.y = expf(v.y - M);
    v.z = expf(v.z - M); v.w = expf(v.w - M);
    float s = v.x + v.y + v.z + v.w;
#pragma unroll
    for (int o = 16; o; o >>= 1) s += __shfl_xor_sync(0xffffffffu, s, o);
    if (lane == 0) red[wid] = s;
    __syncthreads();
    if (tid < 8) {
        s = red[tid];
#pragma unroll
        for (int o = 4; o; o >>= 1) s += __shfl_xor_sync(0xffu, s, o);
        if (tid == 0) red[0] = s;
    }
    __syncthreads();
    const float inv = 1.f / red[0];
    v.x = to_tf32(v.x * inv); v.y = to_tf32(v.y * inv);
    v.z = to_tf32(v.z * inv); v.w = to_tf32(v.w * inv);
    p[tid] = v;
}

// ---------------------------------------------------------------------------
// Weight rounding (fp32 -> rna tf32 values in fp32 container)
// ---------------------------------------------------------------------------
__global__ void round1_kernel(const float* __restrict__ s, float* __restrict__ d, int n4)
{
    int i = blockIdx.x * 256 + threadIdx.x;
    if (i < n4) {
        float4 v = ((const float4*)s)[i];
        v.x = to_tf32(v.x); v.y = to_tf32(v.y);
        v.z = to_tf32(v.z); v.w = to_tf32(v.w);
        ((float4*)d)[i] = v;
    }
}
__global__ void round2_kernel(const float* __restrict__ s0, float* __restrict__ d0,
                              const float* __restrict__ s1, float* __restrict__ d1, int n4)
{
    int i = blockIdx.x * 256 + threadIdx.x;
    const float* s; float* d; int off;
    if (i < n4) { s = s0; d = d0; off = i; }
    else        { s = s1; d = d1; off = i - n4; }
    float4 v = ((const float4*)s)[off];
    v.x = to_tf32(v.x); v.y = to_tf32(v.y);
    v.z = to_tf32(v.z); v.w = to_tf32(v.w);
    ((float4*)d)[off] = v;
}

// ---------------------------------------------------------------------------
// Host launch
// ---------------------------------------------------------------------------
static const int SMEM_KM = 3 * (SA_ELEMS + SBKM_ELEMS) * 4;
static const int SMEM_NN = 3 * (SA_ELEMS + SBNN_ELEMS) * 4;

extern "C" void kernel_launch(void* const* d_in, const int* in_sizes, int n_in,
                              void* d_out, int out_size)
{
    const float* hid   = (const float*)d_in[1];
    const float* amask = (const float*)d_in[2];
    const float* Wq = (const float*)d_in[4];  const float* bq = (const float*)d_in[5];
    const float* Wk = (const float*)d_in[6];  const float* bk = (const float*)d_in[7];
    const float* Wv = (const float*)d_in[8];  const float* bv = (const float*)d_in[9];
    const float* Wo = (const float*)d_in[10]; const float* bo = (const float*)d_in[11];
    const float* l1w = (const float*)d_in[12]; const float* l1b = (const float*)d_in[13];
    const float* l2w = (const float*)d_in[14]; const float* l2b = (const float*)d_in[15];
    const float* W1 = (const float*)d_in[16]; const float* b1 = (const float*)d_in[17];
    const float* W2 = (const float*)d_in[18]; const float* b2 = (const float*)d_in[19];
    float* out = (float*)d_out;

    void* p;
    cudaGetSymbolAddress(&p, g_xln1);  float* xln1 = (float*)p;
    cudaGetSymbolAddress(&p, g_q);     float* q    = (float*)p;
    cudaGetSymbolAddress(&p, g_k);     float* k    = (float*)p;
    cudaGetSymbolAddress(&p, g_v);     float* v    = (float*)p;
    cudaGetSymbolAddress(&p, g_scores);float* sc   = (float*)p;
    cudaGetSymbolAddress(&p, g_attn);  float* attn = (float*)p;
    cudaGetSymbolAddress(&p, g_hidden);float* hd2  = (float*)p;
    cudaGetSymbolAddress(&p, g_yln2);  float* yln2 = (float*)p;
    cudaGetSymbolAddress(&p, g_mid);   float* mid  = (float*)p;
    cudaGetSymbolAddress(&p, g_wqkv);  float* wqkv = (float*)p;
    cudaGetSymbolAddress(&p, g_wo);    float* wo   = (float*)p;
    cudaGetSymbolAddress(&p, g_w1);    float* w1   = (float*)p;
    cudaGetSymbolAddress(&p, g_w2);    float* w2   = (float*)p;

    cudaFuncSetAttribute((const void*)gemm_big<EPI_QKV3>,   cudaFuncAttributeMaxDynamicSharedMemorySize, GB_SMEM);
    cudaFuncSetAttribute((const void*)gemm_big<EPI_BIASRES>,cudaFuncAttributeMaxDynamicSharedMemorySize, GB_SMEM);
    cudaFuncSetAttribute((const void*)gemm_big<EPI_GELU>,   cudaFuncAttributeMaxDynamicSharedMemorySize, GB_SMEM);
    cudaFuncSetAttribute((const void*)gemm_k<true,  EPI_SCORES>, cudaFuncAttributeMaxDynamicSharedMemorySize, SMEM_KM);
    cudaFuncSetAttribute((const void*)gemm_k<false, EPI_RND>,    cudaFuncAttributeMaxDynamicSharedMemorySize, SMEM_NN);

    const float qscale = 0.08838834764831845f;  // 128^-0.5
    const int n4w = DD * DD / 4;                // 1M float4 per attn weight
    const int n4m = II * DD / 4;                // 4M float4 per MLP weight

    // 0..3) weight rounding (4 launches so ncu -s 5 lands on the QKV GEMM)
    round2_kernel<<<2 * n4w / 256, 256>>>(Wq, wqkv, Wk, wqkv + DD*DD, n4w);
    round2_kernel<<<2 * n4w / 256, 256>>>(Wv, wqkv + 2*DD*DD, Wo, wo, n4w);
    round1_kernel<<<n4m / 256, 256>>>(W1, w1, n4m);
    round1_kernel<<<n4m / 256, 256>>>(W2, w2, n4m);

    // 4) LN1
    ln_kernel<<<MTOK, 256>>>(hid, l1w, l1b, xln1);

    // 5) fused QKV projection: [4096 x 6144] = xln1 @ [Wq|Wk|Wv]^T  <-- profiled
    gemm_big<EPI_QKV3><<<dim3(3*DD/256, MTOK/128), 256, GB_SMEM>>>(
        xln1, wqkv, q, k, v, DD, DD, bq, bk, bv, nullptr, qscale);

    // 6) scores = q @ k^T (+mask)
    gemm_k<true, EPI_SCORES><<<dim3(8, 8, BB*HH), 256, SMEM_KM>>>(
        q, k, sc, DD, DD, SS, 4,
        (long)SS*DD, HDIM, (long)SS*DD, HDIM,
        (long)HH*SS*SS, (long)SS*SS, (long)SS, 0, HH,
        nullptr, amask, 1.0f);

    // 7) softmax
    softmax_kernel<<<BB*HH*SS, 256>>>(sc);

    // 8) attn = P @ V
    gemm_k<false, EPI_RND><<<dim3(1, 8, BB*HH), 256, SMEM_NN>>>(
        sc, v, attn, SS, DD, DD, 32,
        (long)HH*SS*SS, (long)SS*SS, (long)SS*DD, HDIM,
        (long)SS*DD, HDIM, 0, 0, HH,
        nullptr, nullptr, 1.0f);

    // 9) hidden = residual + attn @ Wo^T + bo
    gemm_big<EPI_BIASRES><<<dim3(DD/256, MTOK/128), 256, GB_SMEM>>>(
        attn, wo, hd2, nullptr, nullptr, DD, DD, bo, nullptr, nullptr, hid, 1.0f);

    // 10) LN2
    ln_kernel<<<MTOK, 256>>>(hd2, l2w, l2b, yln2);

    // 11) mid = gelu(yln2 @ W1^T + b1)
    gemm_big<EPI_GELU><<<dim3(II/256, MTOK/128), 256, GB_SMEM>>>(
        yln2, w1, mid, nullptr, nullptr, DD, II, b1, nullptr, nullptr, nullptr, 1.0f);

    // 12) out = hidden + mid @ W2^T + b2 (K=8192)
    gemm_big<EPI_BIASRES><<<dim3(DD/256, MTOK/128), 256, GB_SMEM>>>(
        mid, w2, out, nullptr, nullptr, II, DD, b2, nullptr, nullptr, hd2, 1.0f);
}

// round 6
// speedup vs baseline: 1.2616x; 1.1047x over previous
#include <cuda_runtime.h>
#include <cstdint>
#include <cmath>

// ---------------------------------------------------------------------------
// Problem constants
// ---------------------------------------------------------------------------
#define BB 4
#define SS 1024
#define DD 2048
#define HH 16
#define HDIM 128
#define II 8192
#define MTOK (BB*SS)

// ---------------------------------------------------------------------------
// Scratch
// ---------------------------------------------------------------------------
__device__ __align__(256) float g_xln1 [MTOK*DD];
__device__ __align__(256) float g_q    [MTOK*DD];
__device__ __align__(256) float g_k    [MTOK*DD];
__device__ __align__(256) float g_v    [MTOK*DD];
__device__ __align__(256) float g_scores[(long)BB*HH*SS*SS];
__device__ __align__(256) float g_attn [MTOK*DD];
__device__ __align__(256) float g_hidden[MTOK*DD];
__device__ __align__(256) float g_yln2 [MTOK*DD];
__device__ __align__(256) float g_mid  [MTOK*II];
__device__ __align__(256) float g_wqkv[3*DD*DD];   // packed fragments, N=6144 (NB8=768)
__device__ __align__(256) float g_wo[DD*DD];       // packed, NB8=256
__device__ __align__(256) float g_w1[II*DD];       // packed, NB8=1024, K=2048
__device__ __align__(256) float g_w2[DD*II];       // packed, NB8=256,  K=8192

// ---------------------------------------------------------------------------
// Helpers
// ---------------------------------------------------------------------------
__device__ __forceinline__ float to_tf32(float x) {
    float r;
    asm("cvt.rna.tf32.f32 %0, %1;" : "=f"(r) : "f"(x));
    return r;
}
__device__ __forceinline__ void cpa16(void* sdst, const void* gsrc) {
    uint32_t s = (uint32_t)__cvta_generic_to_shared(sdst);
    asm volatile("cp.async.cg.shared.global [%0], [%1], 16;" :: "r"(s), "l"(gsrc));
}
__device__ __forceinline__ void cp_commit() { asm volatile("cp.async.commit_group;"); }
__device__ __forceinline__ void cp_wait2()  { asm volatile("cp.async.wait_group 2;"); }

__device__ __forceinline__ void mma_tf32(float c[4], const float a[4], const float b[2]) {
    const uint32_t* A = reinterpret_cast<const uint32_t*>(a);
    const uint32_t* Bp = reinterpret_cast<const uint32_t*>(b);
    asm volatile(
        "mma.sync.aligned.m16n8k8.row.col.f32.tf32.tf32.f32 "
        "{%0,%1,%2,%3}, {%4,%5,%6,%7}, {%8,%9}, {%0,%1,%2,%3};"
        : "+f"(c[0]), "+f"(c[1]), "+f"(c[2]), "+f"(c[3])
        : "r"(A[0]), "r"(A[1]), "r"(A[2]), "r"(A[3]), "r"(Bp[0]), "r"(Bp[1]));
}

enum { EPI_QKV3 = 0, EPI_SCORES = 1, EPI_RND = 2, EPI_BIASRES = 3, EPI_GELU = 4 };

// ===========================================================================
// gemm_big: C[M,N] = A[M,K] @ Wpacked^T, fused epilogue.
// CTA 128x256x32, 8 warps (2M x 4N), warp tile 64x64, acc[4][8][4].
// A: K-major, smem stride 36 (conflict-free fragment loads).
// B: fragment-packed global layout with baked-in bank swizzle:
//   element (n,k): g=n&7, n8=n>>3, kt=k>>5, ks=(k>>3)&3, h=(k>>2)&1, t=k&3
//   off = (((kt*NB8tot + n8)*32 + g*4+t)*8) + ((ks*2 + h) ^ ((g&3)<<1))
// smem copy is purely linear 32KB; LDS.64 reads are fully conflict-free
// (bank = 8t + 2*perm_g(ks), 16 disjoint even-bank pairs per phase).
// Register double-buffered fragments; 3-stage cp.async pipeline.
// ===========================================================================
#define GB_AS 36
#define GB_A_FLOATS (128*GB_AS)                 // 4608 per stage
#define GB_B_FLOATS (256*32)                    // 8192 per stage
#define GB_SMEM (3*(GB_A_FLOATS+GB_B_FLOATS)*4) // 153600 bytes

template<int EPI>
__global__ void __launch_bounds__(256, 1) gemm_big(
    const float* __restrict__ A, const float* __restrict__ Bp,
    float* __restrict__ C0, float* __restrict__ C1, float* __restrict__ C2,
    int K, int NB8tot, int ldc,
    const float* __restrict__ bias0, const float* __restrict__ bias1,
    const float* __restrict__ bias2, const float* __restrict__ extra, float scale)
{
    extern __shared__ float sm[];
    float* sA = sm;
    float* sB = sm + 3 * GB_A_FLOATS;

    const int tid = threadIdx.x;
    const int ntk = K >> 5;

    const float* Ab = A + (long)blockIdx.y * 128 * K;
    const long bslice = (long)blockIdx.x * 32 * 256;   // CTA's n8 window within a ktile slab

    auto issue = [&](int kt, int stg) {
        float* sa = sA + stg * GB_A_FLOATS;
        const float* ag = Ab + (long)kt * 32;
#pragma unroll
        for (int i = 0; i < 4; i++) {
            int c = tid + i * 256;                 // 0..1023 chunks of A tile
            int r = c >> 3, cc = (c & 7) * 4;
            cpa16(sa + r * GB_AS + cc, ag + (long)r * K + cc);
        }
        float* sb = sB + stg * GB_B_FLOATS;
        const float* bg = Bp + (long)kt * NB8tot * 256 + bslice;
#pragma unroll
        for (int i = 0; i < 8; i++) {
            int c = tid + i * 256;                 // 0..2047 chunks: pure linear copy
            cpa16(sb + c * 4, bg + (long)c * 4);
        }
    };

    const int warp = tid >> 5, lane = tid & 31;
    const int wm = (warp & 1) * 64;       // 2 warps along M
    const int wnidx = warp >> 1;          // 4 warps along N
    const int g = lane >> 2, t = lane & 3;
    const int bswz = (g & 3) << 1;        // ks-permutation baked into packed layout

    float acc[4][8][4];
#pragma unroll
    for (int mt = 0; mt < 4; mt++)
#pragma unroll
        for (int nt = 0; nt < 8; nt++)
#pragma unroll
            for (int i = 0; i < 4; i++) acc[mt][nt][i] = 0.f;

    issue(0, 0); cp_commit();
    issue(1, 1); cp_commit();

    for (int it = 0; it < ntk; ++it) {
        const int stg = it % 3;
        if (it + 2 < ntk) issue(it + 2, (it + 2) % 3);
        cp_commit();
        cp_wait2();
        __syncthreads();

        const float* sa  = sA + stg * GB_A_FLOATS;
        const float* sbw = sB + stg * GB_B_FLOATS + wnidx * 2048 + lane * 8;

        float af[2][4][4];
        float bf[2][8][2];

        // prime ks=0 fragments
#pragma unroll
        for (int mt = 0; mt < 4; mt++) {
            const int r0 = wm + mt * 16 + g;
            af[0][mt][0] = sa[r0 * GB_AS + t];
            af[0][mt][1] = sa[(r0 + 8) * GB_AS + t];
            af[0][mt][2] = sa[r0 * GB_AS + t + 4];
            af[0][mt][3] = sa[(r0 + 8) * GB_AS + t + 4];
        }
#pragma unroll
        for (int nt = 0; nt < 8; nt++) {
            float2 b = *(const float2*)(sbw + nt * 256 + (0 ^ bswz));
            bf[0][nt][0] = b.x; bf[0][nt][1] = b.y;
        }

#pragma unroll
        for (int ks = 0; ks < 4; ks++) {
            const int cur = ks & 1, nxt = cur ^ 1;
            if (ks < 3) {
                const int k0 = (ks + 1) * 8;
#pragma unroll
                for (int mt = 0; mt < 4; mt++) {
                    const int r0 = wm + mt * 16 + g;
                    af[nxt][mt][0] = sa[r0 * GB_AS + k0 + t];
                    af[nxt][mt][1] = sa[(r0 + 8) * GB_AS + k0 + t];
                    af[nxt][mt][2] = sa[r0 * GB_AS + k0 + t + 4];
                    af[nxt][mt][3] = sa[(r0 + 8) * GB_AS + k0 + t + 4];
                }
                const int bo = ((ks + 1) * 2) ^ bswz;
#pragma unroll
                for (int nt = 0; nt < 8; nt++) {
                    float2 b = *(const float2*)(sbw + nt * 256 + bo);
                    bf[nxt][nt][0] = b.x; bf[nxt][nt][1] = b.y;
                }
            }
#pragma unroll
            for (int mt = 0; mt < 4; mt++)
#pragma unroll
                for (int nt = 0; nt < 8; nt++)
                    mma_tf32(acc[mt][nt], af[cur][mt], bf[cur][nt]);
        }
        __syncthreads();
    }

    // ---------------- epilogue ----------------
    const int wn = wnidx * 64;
    const int nbase = blockIdx.x * 256;
    const int mbase = blockIdx.y * 128 + wm;

    float* dst = C0;
    const float* bs = bias0;
    float sc = scale;
    int nloc = nbase;
    if (EPI == EPI_QKV3) {
        const int seg = nbase >> 11;              // CTA fully inside one of q/k/v
        nloc = nbase & 2047;
        if (seg == 1) { dst = C1; bs = bias1; sc = 1.0f; }
        else if (seg == 2) { dst = C2; bs = bias2; sc = 1.0f; }
    }

#pragma unroll
    for (int mt = 0; mt < 4; mt++) {
#pragma unroll
        for (int half = 0; half < 2; half++) {
            const int row = mbase + mt * 16 + g + half * 8;
            const long crow = (long)row * ldc;
#pragma unroll
            for (int nt = 0; nt < 8; nt++) {
                const int cc = wn + nt * 8 + 2 * t;
                const int col = nloc + cc;
                float v0 = acc[mt][nt][half * 2 + 0];
                float v1 = acc[mt][nt][half * 2 + 1];
                if (EPI == EPI_QKV3) {
                    v0 = to_tf32((v0 + bs[col]) * sc);
                    v1 = to_tf32((v1 + bs[col + 1]) * sc);
                } else if (EPI == EPI_BIASRES) {
                    v0 += bs[col]     + extra[crow + col];
                    v1 += bs[col + 1] + extra[crow + col + 1];
                } else if (EPI == EPI_GELU) {
                    v0 += bs[col];
                    v1 += bs[col + 1];
                    v0 = to_tf32(0.5f * v0 * (1.f + erff(v0 * 0.7071067811865476f)));
                    v1 = to_tf32(0.5f * v1 * (1.f + erff(v1 * 0.7071067811865476f)));
                }
                *(float2*)(dst + crow + col) = make_float2(v0, v1);
            }
        }
    }
}

// ===========================================================================
// SIMT GEMM for attention (scores QK^T and P@V) — unchanged (proven)
// ===========================================================================
#define SA_STRIDE 36
#define SBNN_STRIDE 136
#define SA_ELEMS (128*SA_STRIDE)
#define SBKM_ELEMS (128*SA_STRIDE)
#define SBNN_ELEMS (32*SBNN_STRIDE)

template<bool BKM, int EPI>
__global__ void __launch_bounds__(256, 1) gemm_k(
    const float* __restrict__ A, const float* __restrict__ Bm, float* __restrict__ C,
    int lda, int ldb, int ldc, int ntk,
    long aB, long aH, long bB, long bH, long cB, long cH, long eB, long eH, int Hdiv,
    const float* __restrict__ bias, const float* __restrict__ extra, float scale)
{
    extern __shared__ float sm[];
    float* sA = sm;
    float* sB = sm + 3 * SA_ELEMS;

    const int tid = threadIdx.x;
    const int z = blockIdx.z;
    const int bz = z / Hdiv, hz = z - bz * Hdiv;

    const float* Ag = A + bz * aB + hz * aH + (long)(blockIdx.y * 128) * lda;
    const float* Bg;
    if (BKM) Bg = Bm + bz * bB + hz * bH + (long)(blockIdx.x * 128) * ldb;
    else     Bg = Bm + bz * bB + hz * bH + blockIdx.x * 128;

    const int ar = tid >> 3, ac = (tid & 7) * 4;
    const int br = BKM ? (tid >> 3) : (tid >> 5);
    const int bc = BKM ? ((tid & 7) * 4) : ((tid & 31) * 4);

    auto issue = [&](int kt, int stg) {
        const float* a0 = Ag + (long)kt * 32 + ac;
        float* sa = sA + stg * SA_ELEMS;
#pragma unroll
        for (int p = 0; p < 4; p++)
            cpa16(sa + (ar + p * 32) * SA_STRIDE + ac, a0 + (long)(ar + p * 32) * lda);
        if (BKM) {
            const float* b0 = Bg + (long)kt * 32 + bc;
            float* sb = sB + stg * SBKM_ELEMS;
#pragma unroll
            for (int p = 0; p < 4; p++)
                cpa16(sb + (br + p * 32) * SA_STRIDE + bc, b0 + (long)(br + p * 32) * ldb);
        } else {
            const float* b0 = Bg + (long)kt * 32 * ldb + bc;
            float* sb = sB + stg * SBNN_ELEMS;
#pragma unroll
            for (int p = 0; p < 4; p++)
                cpa16(sb + (br + p * 8) * SBNN_STRIDE + bc, b0 + (long)(br + p * 8) * ldb);
        }
    };

    const int warp = tid >> 5, lane = tid & 31;
    const int wm = (warp & 3) * 32;
    const int wn = (warp >> 2) * 64;
    const int g = lane >> 2, t = lane & 3;

    float acc[2][8][4];
#pragma unroll
    for (int mt = 0; mt < 2; mt++)
#pragma unroll
        for (int nt = 0; nt < 8; nt++)
#pragma unroll
            for (int i = 0; i < 4; i++) acc[mt][nt][i] = 0.f;

    issue(0, 0); cp_commit();
    issue(1, 1); cp_commit();

    for (int it = 0; it < ntk; ++it) {
        int stg = it % 3;
        if (it + 2 < ntk) issue(it + 2, (it + 2) % 3);
        cp_commit();
        cp_wait2();
        __syncthreads();

        const float* sa = sA + stg * SA_ELEMS;
        const float* sb = sB + stg * (BKM ? SBKM_ELEMS : SBNN_ELEMS);
#pragma unroll
        for (int ks = 0; ks < 4; ks++) {
            const int k0 = ks * 8;
            float af[2][4];
#pragma unroll
            for (int mt = 0; mt < 2; mt++) {
                int r0 = wm + mt * 16 + g;
                af[mt][0] = sa[r0 * SA_STRIDE + k0 + t];
                af[mt][1] = sa[(r0 + 8) * SA_STRIDE + k0 + t];
                af[mt][2] = sa[r0 * SA_STRIDE + k0 + t + 4];
                af[mt][3] = sa[(r0 + 8) * SA_STRIDE + k0 + t + 4];
            }
            float bf[8][2];
#pragma unroll
            for (int nt = 0; nt < 8; nt++) {
                int c0 = wn + nt * 8 + g;
                if (BKM) {
                    bf[nt][0] = sb[c0 * SA_STRIDE + k0 + t];
                    bf[nt][1] = sb[c0 * SA_STRIDE + k0 + t + 4];
                } else {
                    bf[nt][0] = sb[(k0 + t) * SBNN_STRIDE + c0];
                    bf[nt][1] = sb[(k0 + t + 4) * SBNN_STRIDE + c0];
                }
            }
#pragma unroll
            for (int mt = 0; mt < 2; mt++)
#pragma unroll
                for (int nt = 0; nt < 8; nt++)
                    mma_tf32(acc[mt][nt], af[mt], bf[nt]);
        }
        __syncthreads();
    }

    const long co = bz * cB + hz * cH;
    const long eo = bz * eB + hz * eH;
    const int mbase = blockIdx.y * 128 + wm;
    const int nbase = blockIdx.x * 128 + wn;

#pragma unroll
    for (int mt = 0; mt < 2; mt++) {
#pragma unroll
        for (int half = 0; half < 2; half++) {
            const int row = mbase + mt * 16 + g + half * 8;
#pragma unroll
            for (int nt = 0; nt < 8; nt++) {
                const int col = nbase + nt * 8 + 2 * t;
                float v0 = acc[mt][nt][half * 2 + 0];
                float v1 = acc[mt][nt][half * 2 + 1];
                if (EPI == EPI_SCORES) {
                    if (extra[eo + col]     == 0.f) v0 += -3.4028234663852886e38f;
                    if (extra[eo + col + 1] == 0.f) v1 += -3.4028234663852886e38f;
                } else if (EPI == EPI_RND) {
                    v0 = to_tf32(v0);
                    v1 = to_tf32(v1);
                }
                *(float2*)(C + co + (long)row * ldc + col) = make_float2(v0, v1);
            }
        }
    }
}

// ---------------------------------------------------------------------------
// LayerNorm (tf32-rna rounded output)
// ---------------------------------------------------------------------------
__global__ void ln_kernel(const float* __restrict__ x, const float* __restrict__ w,
                          const float* __restrict__ b, float* __restrict__ out)
{
    __shared__ float s1[8], s2[8];
    const int row = blockIdx.x, tid = threadIdx.x;
    const int lane = tid & 31, wid = tid >> 5;
    const float4* xr = (const float4*)(x + (long)row * DD);
    float4 v0 = xr[tid], v1 = xr[tid + 256];

    float s = v0.x + v0.y + v0.z + v0.w + v1.x + v1.y + v1.z + v1.w;
    float q = v0.x*v0.x + v0.y*v0.y + v0.z*v0.z + v0.w*v0.w
            + v1.x*v1.x + v1.y*v1.y + v1.z*v1.z + v1.w*v1.w;
#pragma unroll
    for (int o = 16; o; o >>= 1) {
        s += __shfl_xor_sync(0xffffffffu, s, o);
        q += __shfl_xor_sync(0xffffffffu, q, o);
    }
    if (lane == 0) { s1[wid] = s; s2[wid] = q; }
    __syncthreads();
    if (tid < 8) {
        s = s1[tid]; q = s2[tid];
#pragma unroll
        for (int o = 4; o; o >>= 1) {
            s += __shfl_xor_sync(0xffu, s, o);
            q += __shfl_xor_sync(0xffu, q, o);
        }
        if (tid == 0) { s1[0] = s; s2[0] = q; }
    }
    __syncthreads();
    const float mu = s1[0] * (1.f / DD);
    const float var = s2[0] * (1.f / DD) - mu * mu;
    const float r = rsqrtf(var + 1e-5f);

    float4 o0, o1;
    int c0 = tid * 4, c1 = (tid + 256) * 4;
    o0.x = to_tf32((v0.x - mu) * r * w[c0+0] + b[c0+0]);
    o0.y = to_tf32((v0.y - mu) * r * w[c0+1] + b[c0+1]);
    o0.z = to_tf32((v0.z - mu) * r * w[c0+2] + b[c0+2]);
    o0.w = to_tf32((v0.w - mu) * r * w[c0+3] + b[c0+3]);
    o1.x = to_tf32((v1.x - mu) * r * w[c1+0] + b[c1+0]);
    o1.y = to_tf32((v1.y - mu) * r * w[c1+1] + b[c1+1]);
    o1.z = to_tf32((v1.z - mu) * r * w[c1+2] + b[c1+2]);
    o1.w = to_tf32((v1.w - mu) * r * w[c1+3] + b[c1+3]);
    float4* orow = (float4*)(out + (long)row * DD);
    orow[tid] = o0; orow[tid + 256] = o1;
}

// ---------------------------------------------------------------------------
// Softmax (tf32-rna rounded probs)
// ---------------------------------------------------------------------------
__global__ void softmax_kernel(float* __restrict__ sc)
{
    __shared__ float red[8];
    const long row = blockIdx.x;
    float4* p = (float4*)(sc + row * (long)SS);
    const int tid = threadIdx.x, lane = tid & 31, wid = tid >> 5;
    float4 v = p[tid];

    float m = fmaxf(fmaxf(v.x, v.y), fmaxf(v.z, v.w));
#pragma unroll
    for (int o = 16; o; o >>= 1) m = fmaxf(m, __shfl_xor_sync(0xffffffffu, m, o));
    if (lane == 0) red[wid] = m;
    __syncthreads();
    if (tid < 8) {
        m = red[tid];
#pragma unroll
        for (int o = 4; o; o >>= 1) m = fmaxf(m, __shfl_xor_sync(0xffu, m, o));
        if (tid == 0) red[0] = m;
    }
    __syncthreads();
    const float M = red[0];
    __syncthreads();

    v.x = expf(v.x - M); v.y = expf(v.y - M);
    v.z = expf(v.z - M); v.w = expf(v.w - M);
    float s = v.x + v.y + v.z + v.w;
#pragma unroll
    for (int o = 16; o; o >>= 1) s += __shfl_xor_sync(0xffffffffu, s, o);
    if (lane == 0) red[wid] = s;
    __syncthreads();
    if (tid < 8) {
        s = red[tid];
#pragma unroll
        for (int o = 4; o; o >>= 1) s += __shfl_xor_sync(0xffu, s, o);
        if (tid == 0) red[0] = s;
    }
    __syncthreads();
    const float inv = 1.f / red[0];
    v.x = to_tf32(v.x * inv); v.y = to_tf32(v.y * inv);
    v.z = to_tf32(v.z * inv); v.w = to_tf32(v.w * inv);
    p[tid] = v;
}

// ---------------------------------------------------------------------------
// Fused round+pack: all 6 weights in ONE launch.
// Reads coalesced float4 from source W[N][K]; writes fragment-packed layout
// with the per-lane bank swizzle baked in. Segments (float4 units of 1M):
//   [0,1) Wq->wqkv(n8off 0)  [1,2) Wk(+256)  [2,3) Wv(+512)
//   [3,4) Wo  [4,8) W1  [8,12) W2
// ---------------------------------------------------------------------------
__device__ __forceinline__ void pack4(const float* __restrict__ src, float* __restrict__ dst,
                                      int K, int NB8tot, int n8off, long s)
{
    const int kq = K >> 2;
    const int n = (int)(s / kq);
    const int k4 = (int)(s - (long)n * kq);
    float4 v = ((const float4*)src)[s];
    float vals[4];
    vals[0] = to_tf32(v.x); vals[1] = to_tf32(v.y);
    vals[2] = to_tf32(v.z); vals[3] = to_tf32(v.w);
    const int gg = n & 7;
    const long n8 = (n >> 3) + n8off;
    const int swz = (gg & 3) << 1;
#pragma unroll
    for (int c = 0; c < 4; c++) {
        const int k = k4 * 4 + c;
        const int kt = k >> 5, ks = (k >> 3) & 3, h = (k >> 2) & 1, t = k & 3;
        const long base = (((long)kt * NB8tot + n8) * 32 + (gg * 4 + t)) * 8;
        dst[base + ((ks * 2 + h) ^ swz)] = vals[c];
    }
}

__global__ void round_pack_all(
    const float* __restrict__ Wq, const float* __restrict__ Wk,
    const float* __restrict__ Wv, const float* __restrict__ Wo,
    const float* __restrict__ W1, const float* __restrict__ W2,
    float* __restrict__ dqkv, float* __restrict__ dwo,
    float* __restrict__ dw1, float* __restrict__ dw2)
{
    const long M1 = 1048576;
    const long i = (long)blockIdx.x * 256 + threadIdx.x;
    if      (i < 1*M1) pack4(Wq, dqkv, DD, 768, 0,   i);
    else if (i < 2*M1) pack4(Wk, dqkv, DD, 768, 256, i - 1*M1);
    else if (i < 3*M1) pack4(Wv, dqkv, DD, 768, 512, i - 2*M1);
    else if (i < 4*M1) pack4(Wo, dwo,  DD, 256, 0,   i - 3*M1);
    else if (i < 8*M1) pack4(W1, dw1,  DD, 1024, 0,  i - 4*M1);
    else               pack4(W2, dw2,  II, 256, 0,   i - 8*M1);
}

// ---------------------------------------------------------------------------
// Host launch
// ---------------------------------------------------------------------------
static const int SMEM_KM = 3 * (SA_ELEMS + SBKM_ELEMS) * 4;
static const int SMEM_NN = 3 * (SA_ELEMS + SBNN_ELEMS) * 4;

extern "C" void kernel_launch(void* const* d_in, const int* in_sizes, int n_in,
                              void* d_out, int out_size)
{
    const float* hid   = (const float*)d_in[1];
    const float* amask = (const float*)d_in[2];
    const float* Wq = (const float*)d_in[4];  const float* bq = (const float*)d_in[5];
    const float* Wk = (const float*)d_in[6];  const float* bk = (const float*)d_in[7];
    const float* Wv = (const float*)d_in[8];  const float* bv = (const float*)d_in[9];
    const float* Wo = (const float*)d_in[10]; const float* bo = (const float*)d_in[11];
    const float* l1w = (const float*)d_in[12]; const float* l1b = (const float*)d_in[13];
    const float* l2w = (const float*)d_in[14]; const float* l2b = (const float*)d_in[15];
    const float* W1 = (const float*)d_in[16]; const float* b1 = (const float*)d_in[17];
    const float* W2 = (const float*)d_in[18]; const float* b2 = (const float*)d_in[19];
    float* out = (float*)d_out;

    void* p;
    cudaGetSymbolAddress(&p, g_xln1);  float* xln1 = (float*)p;
    cudaGetSymbolAddress(&p, g_q);     float* q    = (float*)p;
    cudaGetSymbolAddress(&p, g_k);     float* k    = (float*)p;
    cudaGetSymbolAddress(&p, g_v);     float* v    = (float*)p;
    cudaGetSymbolAddress(&p, g_scores);float* sc   = (float*)p;
    cudaGetSymbolAddress(&p, g_attn);  float* attn = (float*)p;
    cudaGetSymbolAddress(&p, g_hidden);float* hd2  = (float*)p;
    cudaGetSymbolAddress(&p, g_yln2);  float* yln2 = (float*)p;
    cudaGetSymbolAddress(&p, g_mid);   float* mid  = (float*)p;
    cudaGetSymbolAddress(&p, g_wqkv);  float* wqkv = (float*)p;
    cudaGetSymbolAddress(&p, g_wo);    float* wo   = (float*)p;
    cudaGetSymbolAddress(&p, g_w1);    float* w1   = (float*)p;
    cudaGetSymbolAddress(&p, g_w2);    float* w2   = (float*)p;

    cudaFuncSetAttribute((const void*)gemm_big<EPI_QKV3>,   cudaFuncAttributeMaxDynamicSharedMemorySize, GB_SMEM);
    cudaFuncSetAttribute((const void*)gemm_big<EPI_BIASRES>,cudaFuncAttributeMaxDynamicSharedMemorySize, GB_SMEM);
    cudaFuncSetAttribute((const void*)gemm_big<EPI_GELU>,   cudaFuncAttributeMaxDynamicSharedMemorySize, GB_SMEM);
    cudaFuncSetAttribute((const void*)gemm_k<true,  EPI_SCORES>, cudaFuncAttributeMaxDynamicSharedMemorySize, SMEM_KM);
    cudaFuncSetAttribute((const void*)gemm_k<false, EPI_RND>,    cudaFuncAttributeMaxDynamicSharedMemorySize, SMEM_NN);

    const float qscale = 0.08838834764831845f;  // 128^-0.5

    // 1) fused round+pack of all weights (12M float4)
    round_pack_all<<<49152, 256>>>(Wq, Wk, Wv, Wo, W1, W2, wqkv, wo, w1, w2);

    // 2) LN1
    ln_kernel<<<MTOK, 256>>>(hid, l1w, l1b, xln1);

    // 3) fused QKV projection [4096 x 6144]  <-- our launch #3 (ncu's #6)
    gemm_big<EPI_QKV3><<<dim3(3*DD/256, MTOK/128), 256, GB_SMEM>>>(
        xln1, wqkv, q, k, v, DD, 768, DD, bq, bk, bv, nullptr, qscale);

    // 4) scores = q @ k^T (+mask)
    gemm_k<true, EPI_SCORES><<<dim3(8, 8, BB*HH), 256, SMEM_KM>>>(
        q, k, sc, DD, DD, SS, 4,
        (long)SS*DD, HDIM, (long)SS*DD, HDIM,
        (long)HH*SS*SS, (long)SS*SS, (long)SS, 0, HH,
        nullptr, amask, 1.0f);

    // 5) softmax
    softmax_kernel<<<BB*HH*SS, 256>>>(sc);

    // 6) attn = P @ V
    gemm_k<false, EPI_RND><<<dim3(1, 8, BB*HH), 256, SMEM_NN>>>(
        sc, v, attn, SS, DD, DD, 32,
        (long)HH*SS*SS, (long)SS*SS, (long)SS*DD, HDIM,
        (long)SS*DD, HDIM, 0, 0, HH,
        nullptr, nullptr, 1.0f);

    // 7) hidden = residual + attn @ Wo^T + bo
    gemm_big<EPI_BIASRES><<<dim3(DD/256, MTOK/128), 256, GB_SMEM>>>(
        attn, wo, hd2, nullptr, nullptr, DD, 256, DD, bo, nullptr, nullptr, hid, 1.0f);

    // 8) LN2
    ln_kernel<<<MTOK, 256>>>(hd2, l2w, l2b, yln2);

    // 9) mid = gelu(yln2 @ W1^T + b1)
    gemm_big<EPI_GELU><<<dim3(II/256, MTOK/128), 256, GB_SMEM>>>(
        yln2, w1, mid, nullptr, nullptr, DD, 1024, II, b1, nullptr, nullptr, nullptr, 1.0f);

    // 10) out = hidden + mid @ W2^T + b2 (K=8192)
    gemm_big<EPI_BIASRES><<<dim3(DD/256, MTOK/128), 256, GB_SMEM>>>(
        mid, w2, out, nullptr, nullptr, II, 256, DD, b2, nullptr, nullptr, hd2, 1.0f);
}